// round 9
// baseline (speedup 1.0000x reference)
#include <cuda_runtime.h>
#include <cuda_bf16.h>
#include <cstdint>

#define B_ 16384
#define K_ 5
#define D_ 512
#define HG_ 16

// ---------------- scratch (static device globals; no allocs allowed) --------
__device__ float  g_x[B_ * D_];
__device__ float  g_fused[B_ * D_];
__device__ float  g_u[2 * B_ * D_];
__device__ float  g_v[2 * B_ * D_];
__device__ double g_sum[5 * D_];
__device__ double g_sq[5 * D_];
__device__ float  g_scl[5 * D_];
__device__ float  g_sft[5 * D_];
// W^T hi/lo bf16, 3 slots: 0=mg_w 1=ph_w1 2=ph_w2   layout [n][k]
__device__ __nv_bfloat16 g_wth[3 * D_ * D_];
__device__ __nv_bfloat16 g_wtl[3 * D_ * D_];

__device__ __forceinline__ float gelu_tanh(float x) {
    float x3 = x * x * x;
    float t  = tanhf(0.7978845608028654f * (x + 0.044715f * x3));
    return 0.5f * x * (1.0f + t);
}

// --- bitwise replication of XLA:CPU's vectorized f32 exp (Cephes expf) ------
__device__ __forceinline__ float xla_expf(float x) {
    float xx = fminf(fmaxf(x, -88.3762626647949f), 88.3762626647950f);
    float z  = floorf(__fadd_rn(__fmul_rn(1.44269504088896341f, xx), 0.5f));
    xx = __fsub_rn(xx, __fmul_rn(z, 0.693359375f));
    xx = __fsub_rn(xx, __fmul_rn(z, -2.12194440e-4f));
    float x2 = __fmul_rn(xx, xx);
    float y  = 1.9875691500E-4f;
    y = __fadd_rn(__fmul_rn(y, xx), 1.3981999507E-3f);
    y = __fadd_rn(__fmul_rn(y, xx), 8.3334519073E-3f);
    y = __fadd_rn(__fmul_rn(y, xx), 4.1665795894E-2f);
    y = __fadd_rn(__fmul_rn(y, xx), 1.6666665459E-1f);
    y = __fadd_rn(__fmul_rn(y, xx), 5.0000001201E-1f);
    y = __fadd_rn(__fmul_rn(y, x2), xx);
    y = __fadd_rn(y, 1.0f);
    return ldexpf(y, (int)z);
}
__device__ __forceinline__ float xla_sigmoid(float x) {
    return __fdiv_rn(1.0f, __fadd_rn(1.0f, xla_expf(-x)));
}

__device__ __forceinline__ uint32_t pack_bf2(float a, float b) {
    __nv_bfloat162 h = __floats2bfloat162_rn(a, b);
    return *reinterpret_cast<uint32_t*>(&h);
}

// mma.sync m16n8k16 bf16: D(f32) += A(bf16,row) * B(bf16,col)
__device__ __forceinline__ void mma_bf16(float* d, const uint32_t* a,
                                         uint32_t b0, uint32_t b1) {
    asm volatile(
        "mma.sync.aligned.m16n8k16.row.col.f32.bf16.bf16.f32 "
        "{%0,%1,%2,%3}, {%4,%5,%6,%7}, {%8,%9}, {%0,%1,%2,%3};"
        : "+f"(d[0]), "+f"(d[1]), "+f"(d[2]), "+f"(d[3])
        : "r"(a[0]), "r"(a[1]), "r"(a[2]), "r"(a[3]), "r"(b0), "r"(b1));
}

// ---------------------------------------------------------------------------
__global__ void zero_stats_k() {
    int i = blockIdx.x * blockDim.x + threadIdx.x;
    if (i < 5 * D_) { g_sum[i] = 0.0; g_sq[i] = 0.0; }
}

// W [k][n] fp32 -> W^T hi/lo bf16 [n][k]
__global__ void wconv_k(const float* __restrict__ W, int slot) {
    int idx = blockIdx.x * blockDim.x + threadIdx.x;
    if (idx >= D_ * D_) return;
    int n = idx >> 9, k = idx & 511;
    float v = W[k * D_ + n];
    __nv_bfloat16 h = __float2bfloat16(v);
    float r = v - __bfloat162float(h);
    g_wth[slot * D_ * D_ + idx] = h;
    g_wtl[slot * D_ * D_ + idx] = __float2bfloat16(r);
}

__global__ void row_kernel(const float* __restrict__ img, const float* __restrict__ txt,
                           const float* __restrict__ w1, const float* __restrict__ b1,
                           const float* __restrict__ w2, const float* __restrict__ b2,
                           const float* __restrict__ cw, const float* __restrict__ cb)
{
    int w    = (blockIdx.x * blockDim.x + threadIdx.x) >> 5;
    int lane = threadIdx.x & 31;
    if (w >= B_) return;

    const float* ip = img + (size_t)w * D_;
    float  iv[16];
    double isq = 0.0;
#pragma unroll
    for (int i = 0; i < 16; i++) {
        iv[i] = ip[lane + 32 * i];
        isq += (double)iv[i] * (double)iv[i];
    }
#pragma unroll
    for (int o = 16; o; o >>= 1) isq += __shfl_xor_sync(0xffffffffu, isq, o);
    float inorm = fmaxf(sqrtf((float)isq), 1e-12f);

    float ivn[16];
#pragma unroll
    for (int i = 0; i < 16; i++) ivn[i] = __fdiv_rn(iv[i], inorm);

    float tv[K_][16];
    float sim[K_];
#pragma unroll
    for (int k = 0; k < K_; k++) {
        const float* tp = txt + ((size_t)w * K_ + k) * D_;
        double tsq = 0.0;
#pragma unroll
        for (int i = 0; i < 16; i++) {
            float t  = tp[lane + 32 * i];
            tv[k][i] = t;
            tsq += (double)t * (double)t;
        }
#pragma unroll
        for (int o = 16; o; o >>= 1) tsq += __shfl_xor_sync(0xffffffffu, tsq, o);
        float tnorm = fmaxf(sqrtf((float)tsq), 1e-12f);

        double dot = 0.0;
#pragma unroll
        for (int i = 0; i < 16; i++) {
            float tn = __fdiv_rn(tv[k][i], tnorm);
            dot += (double)__fmul_rn(ivn[i], tn);
        }
#pragma unroll
        for (int o = 16; o; o >>= 1) dot += __shfl_xor_sync(0xffffffffu, dot, o);
        sim[k] = (float)dot;
    }

    float wt[K_];
#pragma unroll
    for (int k = 0; k < K_; k++) {
        float acc = 0.0f;
#pragma unroll
        for (int j = 0; j < HG_; j++) {
            float h = fmaxf(__fadd_rn(__fmul_rn(sim[k], w1[j]), b1[j]), 0.0f);
            acc = __fadd_rn(acc, __fmul_rn(h, w2[j]));
        }
        acc   = __fadd_rn(acc, b2[0]);
        wt[k] = xla_sigmoid(acc);
    }

    float coef[K_];
#pragma unroll
    for (int p = 0; p < K_; p++) {
        int r = 0;
#pragma unroll
        for (int q = 0; q < K_; q++)
            r += (wt[q] > wt[p]) || (wt[q] == wt[p] && q < p);
        coef[p] = cw[r] * wt[p];
    }

    float  cbv = cb[0];
    float* xo  = g_x + (size_t)w * D_;
#pragma unroll
    for (int i = 0; i < 16; i++) {
        float s = cbv;
#pragma unroll
        for (int p = 0; p < K_; p++) s = fmaf(coef[p], tv[p][i], s);
        xo[lane + 32 * i] = s;
    }
}

__global__ void colstats_k(const float* __restrict__ A, int rows, int set) {
    int c     = threadIdx.x;
    int chunk = rows / gridDim.x;
    const float* p = A + (size_t)blockIdx.x * chunk * D_ + c;
    float s0 = 0.f, s1 = 0.f, q0 = 0.f, q1 = 0.f;
#pragma unroll 8
    for (int r = 0; r < chunk; r += 2) {
        float v0 = p[(size_t)r * D_];
        float v1 = p[(size_t)(r + 1) * D_];
        s0 += v0; q0 = fmaf(v0, v0, q0);
        s1 += v1; q1 = fmaf(v1, v1, q1);
    }
    atomicAdd(&g_sum[set * D_ + c], (double)(s0 + s1));
    atomicAdd(&g_sq[set * D_ + c], (double)(q0 + q1));
}

__global__ void finalize_k(int set, const float* __restrict__ g, const float* __restrict__ b,
                           float inv) {
    int   c    = threadIdx.x;
    float mean = (float)(g_sum[set * D_ + c] * inv);
    float ex2  = (float)(g_sq[set * D_ + c] * inv);
    float var  = ex2 - mean * mean;
    float sc   = g[c] * rsqrtf(var + 1e-5f);
    g_scl[set * D_ + c] = sc;
    g_sft[set * D_ + c] = b[c] - mean * sc;
}

// ---------------- tensor-core GEMM via mma.sync (bf16 hi/lo split) ----------
// C[m,n] = act( bn(A)[m,:] @ W + bias ),  W pre-transposed/split [n][k].
// CTA tile 128x128, 256 thr = 8 warps (4M x 2N), BK=32, double-buffered smem.
// 1-D grid, n-fastest decode: n0 = (bid&3)*128, m0 = (bid>>2)*128  -> A L2 reuse.
#define ST_ 40
#define STAGE_BYTES (4 * 128 * ST_ * 2)   // 40960: Ah Al Bh Bl @ 10240 each
#define GEMM_DSMEM  (2 * STAGE_BYTES)     // 81920

__device__ __forceinline__ void stage_fill(
    char* st, int arow, int kh, int k0,
    const float* __restrict__ scp, const float* __restrict__ shp,
    const float4* af, uint4 pbh0, uint4 pbh1, uint4 pbl0, uint4 pbl1)
{
    float x[16];
#pragma unroll
    for (int q = 0; q < 4; q++) {
        float4 s4 = *(const float4*)&scp[k0 + kh + q * 4];
        float4 h4 = *(const float4*)&shp[k0 + kh + q * 4];
        x[q * 4 + 0] = fmaf(af[q].x, s4.x, h4.x);
        x[q * 4 + 1] = fmaf(af[q].y, s4.y, h4.y);
        x[q * 4 + 2] = fmaf(af[q].z, s4.z, h4.z);
        x[q * 4 + 3] = fmaf(af[q].w, s4.w, h4.w);
    }
    uint32_t hp[8], lp[8];
#pragma unroll
    for (int j = 0; j < 8; j++) {
        float a0 = x[2 * j], a1 = x[2 * j + 1];
        __nv_bfloat16 h0 = __float2bfloat16(a0), h1 = __float2bfloat16(a1);
        __nv_bfloat162 hh; hh.x = h0; hh.y = h1;
        hp[j] = *reinterpret_cast<uint32_t*>(&hh);
        lp[j] = pack_bf2(a0 - __bfloat162float(h0), a1 - __bfloat162float(h1));
    }
    char* da = st + arow * (ST_ * 2) + kh * 2;                 // Ah
    *(uint4*)(da)      = *(uint4*)&hp[0];
    *(uint4*)(da + 16) = *(uint4*)&hp[4];
    char* dl = da + 10240;                                     // Al
    *(uint4*)(dl)      = *(uint4*)&lp[0];
    *(uint4*)(dl + 16) = *(uint4*)&lp[4];
    char* db = da + 20480;                                     // Bh
    *(uint4*)(db)      = pbh0;
    *(uint4*)(db + 16) = pbh1;
    char* dbl = da + 30720;                                    // Bl
    *(uint4*)(dbl)      = pbl0;
    *(uint4*)(dbl + 16) = pbl1;
}

__global__ __launch_bounds__(256) void gemm_mma(
    const float* __restrict__ A0, const float* __restrict__ A1, int splitM,
    int set0, int set1,
    const __nv_bfloat16* __restrict__ wth, const __nv_bfloat16* __restrict__ wtl,
    const float* __restrict__ bias, float* __restrict__ C, int doGelu)
{
    extern __shared__ __align__(16) char smem[];

    int tid = threadIdx.x, lane = tid & 31, wid = tid >> 5;
    int bid = blockIdx.x;
    int m0 = (bid >> 2) * 128, n0 = (bid & 3) * 128;   // n-fastest: A tiles L2-resident

    const float *A, *scp, *shp;
    int mb;
    if (m0 < splitM) { A = A0; scp = g_scl + set0 * D_; shp = g_sft + set0 * D_; mb = m0; }
    else             { A = A1; scp = g_scl + set1 * D_; shp = g_sft + set1 * D_; mb = m0 - splitM; }

    int arow = tid >> 1, kh = (tid & 1) * 16;   // each thread: one tile row, 16 k's
    const float*         ap  = A + (size_t)(mb + arow) * D_ + kh;
    const __nv_bfloat16* bhp = wth + (size_t)(n0 + arow) * D_ + kh;
    const __nv_bfloat16* blp = wtl + (size_t)(n0 + arow) * D_ + kh;

    int warpM = wid & 3, warpN = wid >> 2;
    int g = lane >> 2, c2 = (lane & 3) * 2;

    float acc[2][8][4];
#pragma unroll
    for (int i = 0; i < 2; i++)
#pragma unroll
        for (int j = 0; j < 8; j++)
#pragma unroll
            for (int q = 0; q < 4; q++) acc[i][j][q] = 0.f;

    // ---- prologue: fetch + stage slab 0 ----
    float4 af[4];
    uint4  pbh0, pbh1, pbl0, pbl1;
#pragma unroll
    for (int q = 0; q < 4; q++) af[q] = *(const float4*)(ap + q * 4);
    pbh0 = *(const uint4*)(bhp);     pbh1 = *(const uint4*)(bhp + 8);
    pbl0 = *(const uint4*)(blp);     pbl1 = *(const uint4*)(blp + 8);
    stage_fill(smem, arow, kh, 0, scp, shp, af, pbh0, pbh1, pbl0, pbl1);
    __syncthreads();

    for (int kt = 0; kt < 16; kt++) {
        int k0 = kt * 32;
        char* cur = smem + (kt & 1) * STAGE_BYTES;
        // ---- prefetch next slab to registers (LDG in flight during mma) ----
        if (kt < 15) {
#pragma unroll
            for (int q = 0; q < 4; q++) af[q] = *(const float4*)(ap + k0 + 32 + q * 4);
            pbh0 = *(const uint4*)(bhp + k0 + 32);
            pbh1 = *(const uint4*)(bhp + k0 + 40);
            pbl0 = *(const uint4*)(blp + k0 + 32);
            pbl1 = *(const uint4*)(blp + k0 + 40);
        }
        // ---- mma on current stage ----
        char* sAh = cur;
        char* sAl = cur + 10240;
        char* sBh = cur + 20480;
        char* sBl = cur + 30720;
#pragma unroll
        for (int h = 0; h < 2; h++) {
            int ko = h * 16;
            uint32_t Ah[2][4], Al[2][4];
#pragma unroll
            for (int im = 0; im < 2; im++) {
                int r = warpM * 32 + im * 16;
                Ah[im][0] = *(const uint32_t*)(sAh + (r + g) * (ST_ * 2) + (ko + c2) * 2);
                Ah[im][1] = *(const uint32_t*)(sAh + (r + g + 8) * (ST_ * 2) + (ko + c2) * 2);
                Ah[im][2] = *(const uint32_t*)(sAh + (r + g) * (ST_ * 2) + (ko + c2 + 8) * 2);
                Ah[im][3] = *(const uint32_t*)(sAh + (r + g + 8) * (ST_ * 2) + (ko + c2 + 8) * 2);
                Al[im][0] = *(const uint32_t*)(sAl + (r + g) * (ST_ * 2) + (ko + c2) * 2);
                Al[im][1] = *(const uint32_t*)(sAl + (r + g + 8) * (ST_ * 2) + (ko + c2) * 2);
                Al[im][2] = *(const uint32_t*)(sAl + (r + g) * (ST_ * 2) + (ko + c2 + 8) * 2);
                Al[im][3] = *(const uint32_t*)(sAl + (r + g + 8) * (ST_ * 2) + (ko + c2 + 8) * 2);
            }
#pragma unroll
            for (int in = 0; in < 8; in++) {
                int nr = warpN * 64 + in * 8 + g;
                uint32_t bh0 = *(const uint32_t*)(sBh + nr * (ST_ * 2) + (ko + c2) * 2);
                uint32_t bh1 = *(const uint32_t*)(sBh + nr * (ST_ * 2) + (ko + c2 + 8) * 2);
                uint32_t bl0 = *(const uint32_t*)(sBl + nr * (ST_ * 2) + (ko + c2) * 2);
                uint32_t bl1 = *(const uint32_t*)(sBl + nr * (ST_ * 2) + (ko + c2 + 8) * 2);
#pragma unroll
                for (int im = 0; im < 2; im++) {
                    mma_bf16(acc[im][in], Ah[im], bh0, bh1);
                    mma_bf16(acc[im][in], Ah[im], bl0, bl1);
                    mma_bf16(acc[im][in], Al[im], bh0, bh1);
                }
            }
        }
        // ---- stage next slab into the other buffer ----
        if (kt < 15) {
            stage_fill(smem + ((kt + 1) & 1) * STAGE_BYTES, arow, kh, k0 + 32,
                       scp, shp, af, pbh0, pbh1, pbl0, pbl1);
        }
        __syncthreads();
    }

    // ---- epilogue: bias (+gelu), direct stores ----
#pragma unroll
    for (int im = 0; im < 2; im++) {
        int row0 = m0 + warpM * 32 + im * 16 + g;
#pragma unroll
        for (int in = 0; in < 8; in++) {
            int    col = n0 + warpN * 64 + in * 8 + c2;
            float2 bb  = *(const float2*)&bias[col];
            float  v0 = acc[im][in][0] + bb.x, v1 = acc[im][in][1] + bb.y;
            float  v2 = acc[im][in][2] + bb.x, v3 = acc[im][in][3] + bb.y;
            if (doGelu) {
                v0 = gelu_tanh(v0); v1 = gelu_tanh(v1);
                v2 = gelu_tanh(v2); v3 = gelu_tanh(v3);
            }
            float2 w0; w0.x = v0; w0.y = v1;
            float2 w1; w1.x = v2; w1.y = v3;
            *(float2*)&C[(size_t)row0 * D_ + col]       = w0;
            *(float2*)&C[(size_t)(row0 + 8) * D_ + col] = w1;
        }
    }
}

__global__ void l2norm_k(const float* __restrict__ V, float* __restrict__ out) {
    int w    = (blockIdx.x * blockDim.x + threadIdx.x) >> 5;
    int lane = threadIdx.x & 31;
    if (w >= 2 * B_) return;
    const float* p = V + (size_t)w * D_;
    float v[16];
    float s = 0.f;
#pragma unroll
    for (int i = 0; i < 16; i++) { v[i] = p[lane + 32 * i]; s = fmaf(v[i], v[i], s); }
#pragma unroll
    for (int o = 16; o; o >>= 1) s += __shfl_xor_sync(0xffffffffu, s, o);
    float inv = 1.0f / sqrtf(s);
#pragma unroll
    for (int i = 0; i < 16; i++) out[(size_t)w * D_ + lane + 32 * i] = v[i] * inv;
}

// ---------------------------------------------------------------------------
extern "C" void kernel_launch(void* const* d_in, const int* in_sizes, int n_in,
                              void* d_out, int out_size) {
    const float* image    = (const float*)d_in[0];
    const float* text     = (const float*)d_in[1];
    const float* wg_w1    = (const float*)d_in[2];
    const float* wg_b1    = (const float*)d_in[3];
    const float* wg_w2    = (const float*)d_in[4];
    const float* wg_b2    = (const float*)d_in[5];
    const float* conv_w   = (const float*)d_in[6];
    const float* conv_b   = (const float*)d_in[7];
    const float* mg_bn_g  = (const float*)d_in[8];
    const float* mg_bn_b  = (const float*)d_in[9];
    const float* mg_w     = (const float*)d_in[10];
    const float* mg_b     = (const float*)d_in[11];
    const float* ph_bn1_g = (const float*)d_in[12];
    const float* ph_bn1_b = (const float*)d_in[13];
    const float* ph_w1    = (const float*)d_in[14];
    const float* ph_b1    = (const float*)d_in[15];
    const float* ph_bn2_g = (const float*)d_in[16];
    const float* ph_bn2_b = (const float*)d_in[17];
    const float* ph_w2    = (const float*)d_in[18];
    const float* ph_b2    = (const float*)d_in[19];
    float*       out      = (float*)d_out;
    (void)in_sizes; (void)n_in; (void)out_size;

    float *px, *pf, *pu, *pv;
    __nv_bfloat16 *pwh, *pwl;
    cudaGetSymbolAddress((void**)&px, g_x);
    cudaGetSymbolAddress((void**)&pf, g_fused);
    cudaGetSymbolAddress((void**)&pu, g_u);
    cudaGetSymbolAddress((void**)&pv, g_v);
    cudaGetSymbolAddress((void**)&pwh, g_wth);
    cudaGetSymbolAddress((void**)&pwl, g_wtl);

    cudaFuncSetAttribute(gemm_mma, cudaFuncAttributeMaxDynamicSharedMemorySize, GEMM_DSMEM);

    const float invB = 1.0f / (float)B_;

    zero_stats_k<<<(5 * D_ + 255) / 256, 256>>>();
    wconv_k<<<D_ * D_ / 256, 256>>>(mg_w, 0);
    wconv_k<<<D_ * D_ / 256, 256>>>(ph_w1, 1);
    wconv_k<<<D_ * D_ / 256, 256>>>(ph_w2, 2);
    row_kernel<<<B_ / 8, 256>>>(image, text, wg_w1, wg_b1, wg_w2, wg_b2, conv_w, conv_b);

    colstats_k<<<256, 512>>>(image, B_, 0);
    colstats_k<<<256, 512>>>(px, B_, 1);
    finalize_k<<<1, 512>>>(0, ph_bn1_g, ph_bn1_b, invB);
    finalize_k<<<1, 512>>>(1, mg_bn_g, mg_bn_b, invB);

    gemm_mma<<<(B_ / 128) * 4, 256, GEMM_DSMEM>>>(px, nullptr, B_, 1, 1,
                          pwh + 0 * D_ * D_, pwl + 0 * D_ * D_, mg_b, pf, 1);

    colstats_k<<<256, 512>>>(pf, B_, 2);
    finalize_k<<<1, 512>>>(2, ph_bn1_g, ph_bn1_b, invB);

    gemm_mma<<<(2 * B_ / 128) * 4, 256, GEMM_DSMEM>>>(image, pf, B_, 0, 2,
                          pwh + 1 * D_ * D_, pwl + 1 * D_ * D_, ph_b1, pu, 1);

    colstats_k<<<256, 512>>>(pu, B_, 3);
    colstats_k<<<256, 512>>>(pu + (size_t)B_ * D_, B_, 4);
    finalize_k<<<1, 512>>>(3, ph_bn2_g, ph_bn2_b, invB);
    finalize_k<<<1, 512>>>(4, ph_bn2_g, ph_bn2_b, invB);

    gemm_mma<<<(2 * B_ / 128) * 4, 256, GEMM_DSMEM>>>(pu, pu + (size_t)B_ * D_, B_, 3, 4,
                          pwh + 2 * D_ * D_, pwl + 2 * D_ * D_, ph_b2, pv, 0);

    l2norm_k<<<2 * B_ / 8, 256>>>(pv, out);
}

// round 10
// speedup vs baseline: 1.0874x; 1.0874x over previous
#include <cuda_runtime.h>
#include <cuda_bf16.h>
#include <cstdint>

#define B_ 16384
#define K_ 5
#define D_ 512
#define HG_ 16

// ---------------- scratch (static device globals; no allocs allowed) --------
__device__ float  g_x[B_ * D_];
__device__ float  g_fused[B_ * D_];
__device__ float  g_u[2 * B_ * D_];
__device__ float  g_v[2 * B_ * D_];
__device__ double g_sum[5 * D_];
__device__ double g_sq[5 * D_];
__device__ float  g_scl[5 * D_];
__device__ float  g_sft[5 * D_];
// W^T hi/lo bf16, 3 slots: 0=mg_w 1=ph_w1 2=ph_w2   layout [n][k]
__device__ __nv_bfloat16 g_wth[3 * D_ * D_];
__device__ __nv_bfloat16 g_wtl[3 * D_ * D_];

__device__ __forceinline__ float gelu_tanh(float x) {
    float x3 = x * x * x;
    float t  = tanhf(0.7978845608028654f * (x + 0.044715f * x3));
    return 0.5f * x * (1.0f + t);
}

// --- bitwise replication of XLA:CPU's vectorized f32 exp (Cephes expf) ------
__device__ __forceinline__ float xla_expf(float x) {
    float xx = fminf(fmaxf(x, -88.3762626647949f), 88.3762626647950f);
    float z  = floorf(__fadd_rn(__fmul_rn(1.44269504088896341f, xx), 0.5f));
    xx = __fsub_rn(xx, __fmul_rn(z, 0.693359375f));
    xx = __fsub_rn(xx, __fmul_rn(z, -2.12194440e-4f));
    float x2 = __fmul_rn(xx, xx);
    float y  = 1.9875691500E-4f;
    y = __fadd_rn(__fmul_rn(y, xx), 1.3981999507E-3f);
    y = __fadd_rn(__fmul_rn(y, xx), 8.3334519073E-3f);
    y = __fadd_rn(__fmul_rn(y, xx), 4.1665795894E-2f);
    y = __fadd_rn(__fmul_rn(y, xx), 1.6666665459E-1f);
    y = __fadd_rn(__fmul_rn(y, xx), 5.0000001201E-1f);
    y = __fadd_rn(__fmul_rn(y, x2), xx);
    y = __fadd_rn(y, 1.0f);
    return ldexpf(y, (int)z);
}
__device__ __forceinline__ float xla_sigmoid(float x) {
    return __fdiv_rn(1.0f, __fadd_rn(1.0f, xla_expf(-x)));
}

__device__ __forceinline__ uint32_t pack_bf2(float a, float b) {
    __nv_bfloat162 h = __floats2bfloat162_rn(a, b);
    return *reinterpret_cast<uint32_t*>(&h);
}

// mma.sync m16n8k16 bf16: D(f32) += A(bf16,row) * B(bf16,col)
__device__ __forceinline__ void mma_bf16(float* d, const uint32_t* a,
                                         uint32_t b0, uint32_t b1) {
    asm volatile(
        "mma.sync.aligned.m16n8k16.row.col.f32.bf16.bf16.f32 "
        "{%0,%1,%2,%3}, {%4,%5,%6,%7}, {%8,%9}, {%0,%1,%2,%3};"
        : "+f"(d[0]), "+f"(d[1]), "+f"(d[2]), "+f"(d[3])
        : "r"(a[0]), "r"(a[1]), "r"(a[2]), "r"(a[3]), "r"(b0), "r"(b1));
}

__device__ __forceinline__ void ldm_x4(uint32_t* r, uint32_t addr) {
    asm volatile("ldmatrix.sync.aligned.m8n8.x4.shared.b16 {%0,%1,%2,%3}, [%4];"
                 : "=r"(r[0]), "=r"(r[1]), "=r"(r[2]), "=r"(r[3]) : "r"(addr));
}
__device__ __forceinline__ uint32_t smem_a32(const void* p) {
    return (uint32_t)__cvta_generic_to_shared(p);
}

// ---------------------------------------------------------------------------
__global__ void zero_stats_k() {
    int i = blockIdx.x * blockDim.x + threadIdx.x;
    if (i < 5 * D_) { g_sum[i] = 0.0; g_sq[i] = 0.0; }
}

// W [k][n] fp32 -> W^T hi/lo bf16 [n][k]
__global__ void wconv_k(const float* __restrict__ W, int slot) {
    int idx = blockIdx.x * blockDim.x + threadIdx.x;
    if (idx >= D_ * D_) return;
    int n = idx >> 9, k = idx & 511;
    float v = W[k * D_ + n];
    __nv_bfloat16 h = __float2bfloat16(v);
    float r = v - __bfloat162float(h);
    g_wth[slot * D_ * D_ + idx] = h;
    g_wtl[slot * D_ * D_ + idx] = __float2bfloat16(r);
}

__global__ void row_kernel(const float* __restrict__ img, const float* __restrict__ txt,
                           const float* __restrict__ w1, const float* __restrict__ b1,
                           const float* __restrict__ w2, const float* __restrict__ b2,
                           const float* __restrict__ cw, const float* __restrict__ cb)
{
    int w    = (blockIdx.x * blockDim.x + threadIdx.x) >> 5;
    int lane = threadIdx.x & 31;
    if (w >= B_) return;

    const float* ip = img + (size_t)w * D_;
    float  iv[16];
    double isq = 0.0;
#pragma unroll
    for (int i = 0; i < 16; i++) {
        iv[i] = ip[lane + 32 * i];
        isq += (double)iv[i] * (double)iv[i];
    }
#pragma unroll
    for (int o = 16; o; o >>= 1) isq += __shfl_xor_sync(0xffffffffu, isq, o);
    float inorm = fmaxf(sqrtf((float)isq), 1e-12f);

    float ivn[16];
#pragma unroll
    for (int i = 0; i < 16; i++) ivn[i] = __fdiv_rn(iv[i], inorm);

    float tv[K_][16];
    float sim[K_];
#pragma unroll
    for (int k = 0; k < K_; k++) {
        const float* tp = txt + ((size_t)w * K_ + k) * D_;
        double tsq = 0.0;
#pragma unroll
        for (int i = 0; i < 16; i++) {
            float t  = tp[lane + 32 * i];
            tv[k][i] = t;
            tsq += (double)t * (double)t;
        }
#pragma unroll
        for (int o = 16; o; o >>= 1) tsq += __shfl_xor_sync(0xffffffffu, tsq, o);
        float tnorm = fmaxf(sqrtf((float)tsq), 1e-12f);

        double dot = 0.0;
#pragma unroll
        for (int i = 0; i < 16; i++) {
            float tn = __fdiv_rn(tv[k][i], tnorm);
            dot += (double)__fmul_rn(ivn[i], tn);
        }
#pragma unroll
        for (int o = 16; o; o >>= 1) dot += __shfl_xor_sync(0xffffffffu, dot, o);
        sim[k] = (float)dot;
    }

    float wt[K_];
#pragma unroll
    for (int k = 0; k < K_; k++) {
        float acc = 0.0f;
#pragma unroll
        for (int j = 0; j < HG_; j++) {
            float h = fmaxf(__fadd_rn(__fmul_rn(sim[k], w1[j]), b1[j]), 0.0f);
            acc = __fadd_rn(acc, __fmul_rn(h, w2[j]));
        }
        acc   = __fadd_rn(acc, b2[0]);
        wt[k] = xla_sigmoid(acc);
    }

    float coef[K_];
#pragma unroll
    for (int p = 0; p < K_; p++) {
        int r = 0;
#pragma unroll
        for (int q = 0; q < K_; q++)
            r += (wt[q] > wt[p]) || (wt[q] == wt[p] && q < p);
        coef[p] = cw[r] * wt[p];
    }

    float  cbv = cb[0];
    float* xo  = g_x + (size_t)w * D_;
#pragma unroll
    for (int i = 0; i < 16; i++) {
        float s = cbv;
#pragma unroll
        for (int p = 0; p < K_; p++) s = fmaf(coef[p], tv[p][i], s);
        xo[lane + 32 * i] = s;
    }
}

__global__ void colstats_k(const float* __restrict__ A, int rows, int set) {
    int c     = threadIdx.x;
    int chunk = rows / gridDim.x;
    const float* p = A + (size_t)blockIdx.x * chunk * D_ + c;
    float s0 = 0.f, s1 = 0.f, q0 = 0.f, q1 = 0.f;
#pragma unroll 8
    for (int r = 0; r < chunk; r += 2) {
        float v0 = p[(size_t)r * D_];
        float v1 = p[(size_t)(r + 1) * D_];
        s0 += v0; q0 = fmaf(v0, v0, q0);
        s1 += v1; q1 = fmaf(v1, v1, q1);
    }
    atomicAdd(&g_sum[set * D_ + c], (double)(s0 + s1));
    atomicAdd(&g_sq[set * D_ + c], (double)(q0 + q1));
}

__global__ void finalize_k(int set, const float* __restrict__ g, const float* __restrict__ b,
                           float inv) {
    int   c    = threadIdx.x;
    float mean = (float)(g_sum[set * D_ + c] * inv);
    float ex2  = (float)(g_sq[set * D_ + c] * inv);
    float var  = ex2 - mean * mean;
    float sc   = g[c] * rsqrtf(var + 1e-5f);
    g_scl[set * D_ + c] = sc;
    g_sft[set * D_ + c] = b[c] - mean * sc;
}

// ---------------- tensor-core GEMM via mma.sync (bf16 hi/lo split) ----------
// C[m,n] = act( bn(A)[m,:] @ W + bias ),  W pre-transposed/split [n][k].
// CTA tile 128x128, 256 thr = 8 warps (4M x 2N), BK=32, single-buffer smem,
// ldmatrix operand loads. 1-D grid, n-fastest decode for A L2 reuse.
#define ST_ 40
__global__ __launch_bounds__(256) void gemm_mma(
    const float* __restrict__ A0, const float* __restrict__ A1, int splitM,
    int set0, int set1,
    const __nv_bfloat16* __restrict__ wth, const __nv_bfloat16* __restrict__ wtl,
    const float* __restrict__ bias, float* __restrict__ C, int doGelu)
{
    __shared__ __align__(16) char smem[4 * 128 * ST_ * 2];   // Ah Al Bh Bl, 10240B each
    char* sAh = smem;
    char* sAl = smem + 10240;
    char* sBh = smem + 20480;
    char* sBl = smem + 30720;

    int tid = threadIdx.x, lane = tid & 31, wid = tid >> 5;
    int bid = blockIdx.x;
    int m0 = (bid >> 2) * 128, n0 = (bid & 3) * 128;   // n-fastest: A tiles L2-resident

    const float *A, *scp, *shp;
    int mb;
    if (m0 < splitM) { A = A0; scp = g_scl + set0 * D_; shp = g_sft + set0 * D_; mb = m0; }
    else             { A = A1; scp = g_scl + set1 * D_; shp = g_sft + set1 * D_; mb = m0 - splitM; }

    int arow = tid >> 1, kh = (tid & 1) * 16;   // each thread: one tile row, 16 k's
    const float*         ap  = A + (size_t)(mb + arow) * D_ + kh;
    const __nv_bfloat16* bhp = wth + (size_t)(n0 + arow) * D_ + kh;
    const __nv_bfloat16* blp = wtl + (size_t)(n0 + arow) * D_ + kh;

    int warpM = wid & 3, warpN = wid >> 2;
    int g = lane >> 2, c2 = (lane & 3) * 2;

    // ldmatrix lane-address components
    int aRowSel = lane & 15, aColSel = (lane >> 4) * 8;                 // A x4
    int bRowSel = (lane & 7) + (lane >> 4) * 8, bColSel = ((lane >> 3) & 1) * 8; // B x4

    float acc[2][8][4];
#pragma unroll
    for (int i = 0; i < 2; i++)
#pragma unroll
        for (int j = 0; j < 8; j++)
#pragma unroll
            for (int q = 0; q < 4; q++) acc[i][j][q] = 0.f;

    // prefetch k-slab 0
    float4 af[4];
    uint4  pbh0, pbh1, pbl0, pbl1;
#pragma unroll
    for (int q = 0; q < 4; q++) af[q] = *(const float4*)(ap + q * 4);
    pbh0 = *(const uint4*)(bhp);     pbh1 = *(const uint4*)(bhp + 8);
    pbl0 = *(const uint4*)(blp);     pbl1 = *(const uint4*)(blp + 8);

    for (int kt = 0; kt < 16; kt++) {
        int k0 = kt * 32;
        __syncthreads();   // previous slab fully consumed
        // ---- fold BN, split, store A; copy B ----
        {
            float x[16];
#pragma unroll
            for (int q = 0; q < 4; q++) {
                float4 s4 = *(const float4*)&scp[k0 + kh + q * 4];
                float4 h4 = *(const float4*)&shp[k0 + kh + q * 4];
                x[q * 4 + 0] = fmaf(af[q].x, s4.x, h4.x);
                x[q * 4 + 1] = fmaf(af[q].y, s4.y, h4.y);
                x[q * 4 + 2] = fmaf(af[q].z, s4.z, h4.z);
                x[q * 4 + 3] = fmaf(af[q].w, s4.w, h4.w);
            }
            uint32_t hp[8], lp[8];
#pragma unroll
            for (int j = 0; j < 8; j++) {
                float a0 = x[2 * j], a1 = x[2 * j + 1];
                __nv_bfloat16 h0 = __float2bfloat16(a0), h1 = __float2bfloat16(a1);
                __nv_bfloat162 hh; hh.x = h0; hh.y = h1;
                hp[j] = *reinterpret_cast<uint32_t*>(&hh);
                lp[j] = pack_bf2(a0 - __bfloat162float(h0), a1 - __bfloat162float(h1));
            }
            char* da = sAh + arow * (ST_ * 2) + kh * 2;
            *(uint4*)(da)      = *(uint4*)&hp[0];
            *(uint4*)(da + 16) = *(uint4*)&hp[4];
            char* dl = sAl + arow * (ST_ * 2) + kh * 2;
            *(uint4*)(dl)      = *(uint4*)&lp[0];
            *(uint4*)(dl + 16) = *(uint4*)&lp[4];
            char* db = sBh + arow * (ST_ * 2) + kh * 2;
            *(uint4*)(db)      = pbh0;
            *(uint4*)(db + 16) = pbh1;
            char* dbl = sBl + arow * (ST_ * 2) + kh * 2;
            *(uint4*)(dbl)      = pbl0;
            *(uint4*)(dbl + 16) = pbl1;
        }
        __syncthreads();
        // ---- prefetch next slab while mma runs ----
        if (kt < 15) {
#pragma unroll
            for (int q = 0; q < 4; q++) af[q] = *(const float4*)(ap + k0 + 32 + q * 4);
            pbh0 = *(const uint4*)(bhp + k0 + 32);
            pbh1 = *(const uint4*)(bhp + k0 + 40);
            pbl0 = *(const uint4*)(blp + k0 + 32);
            pbl1 = *(const uint4*)(blp + k0 + 40);
        }
        // ---- mma over two k16 halves, ldmatrix operands ----
#pragma unroll
        for (int h = 0; h < 2; h++) {
            int ko = h * 16;
            uint32_t Ah[2][4], Al[2][4];
#pragma unroll
            for (int im = 0; im < 2; im++) {
                int r = warpM * 32 + im * 16;
                uint32_t offA = (uint32_t)(r + aRowSel) * (ST_ * 2) + (ko + aColSel) * 2;
                ldm_x4(Ah[im], smem_a32(sAh + offA));
                ldm_x4(Al[im], smem_a32(sAl + offA));
            }
#pragma unroll
            for (int p = 0; p < 4; p++) {
                int nr0 = warpN * 64 + p * 16;
                uint32_t offB = (uint32_t)(nr0 + bRowSel) * (ST_ * 2) + (ko + bColSel) * 2;
                uint32_t bh[4], bl[4];
                ldm_x4(bh, smem_a32(sBh + offB));
                ldm_x4(bl, smem_a32(sBl + offB));
#pragma unroll
                for (int s = 0; s < 2; s++) {
                    int in = 2 * p + s;
#pragma unroll
                    for (int im = 0; im < 2; im++) {
                        mma_bf16(acc[im][in], Ah[im], bh[2 * s], bh[2 * s + 1]);
                        mma_bf16(acc[im][in], Ah[im], bl[2 * s], bl[2 * s + 1]);
                        mma_bf16(acc[im][in], Al[im], bh[2 * s], bh[2 * s + 1]);
                    }
                }
            }
        }
    }

    // ---- epilogue: bias (+gelu), direct stores ----
#pragma unroll
    for (int im = 0; im < 2; im++) {
        int row0 = m0 + warpM * 32 + im * 16 + g;
#pragma unroll
        for (int in = 0; in < 8; in++) {
            int    col = n0 + warpN * 64 + in * 8 + c2;
            float2 bb  = *(const float2*)&bias[col];
            float  v0 = acc[im][in][0] + bb.x, v1 = acc[im][in][1] + bb.y;
            float  v2 = acc[im][in][2] + bb.x, v3 = acc[im][in][3] + bb.y;
            if (doGelu) {
                v0 = gelu_tanh(v0); v1 = gelu_tanh(v1);
                v2 = gelu_tanh(v2); v3 = gelu_tanh(v3);
            }
            float2 w0; w0.x = v0; w0.y = v1;
            float2 w1; w1.x = v2; w1.y = v3;
            *(float2*)&C[(size_t)row0 * D_ + col]       = w0;
            *(float2*)&C[(size_t)(row0 + 8) * D_ + col] = w1;
        }
    }
}

__global__ void l2norm_k(const float* __restrict__ V, float* __restrict__ out) {
    int w    = (blockIdx.x * blockDim.x + threadIdx.x) >> 5;
    int lane = threadIdx.x & 31;
    if (w >= 2 * B_) return;
    const float* p = V + (size_t)w * D_;
    float v[16];
    float s = 0.f;
#pragma unroll
    for (int i = 0; i < 16; i++) { v[i] = p[lane + 32 * i]; s = fmaf(v[i], v[i], s); }
#pragma unroll
    for (int o = 16; o; o >>= 1) s += __shfl_xor_sync(0xffffffffu, s, o);
    float inv = 1.0f / sqrtf(s);
#pragma unroll
    for (int i = 0; i < 16; i++) out[(size_t)w * D_ + lane + 32 * i] = v[i] * inv;
}

// ---------------------------------------------------------------------------
extern "C" void kernel_launch(void* const* d_in, const int* in_sizes, int n_in,
                              void* d_out, int out_size) {
    const float* image    = (const float*)d_in[0];
    const float* text     = (const float*)d_in[1];
    const float* wg_w1    = (const float*)d_in[2];
    const float* wg_b1    = (const float*)d_in[3];
    const float* wg_w2    = (const float*)d_in[4];
    const float* wg_b2    = (const float*)d_in[5];
    const float* conv_w   = (const float*)d_in[6];
    const float* conv_b   = (const float*)d_in[7];
    const float* mg_bn_g  = (const float*)d_in[8];
    const float* mg_bn_b  = (const float*)d_in[9];
    const float* mg_w     = (const float*)d_in[10];
    const float* mg_b     = (const float*)d_in[11];
    const float* ph_bn1_g = (const float*)d_in[12];
    const float* ph_bn1_b = (const float*)d_in[13];
    const float* ph_w1    = (const float*)d_in[14];
    const float* ph_b1    = (const float*)d_in[15];
    const float* ph_bn2_g = (const float*)d_in[16];
    const float* ph_bn2_b = (const float*)d_in[17];
    const float* ph_w2    = (const float*)d_in[18];
    const float* ph_b2    = (const float*)d_in[19];
    float*       out      = (float*)d_out;
    (void)in_sizes; (void)n_in; (void)out_size;

    float *px, *pf, *pu, *pv;
    __nv_bfloat16 *pwh, *pwl;
    cudaGetSymbolAddress((void**)&px, g_x);
    cudaGetSymbolAddress((void**)&pf, g_fused);
    cudaGetSymbolAddress((void**)&pu, g_u);
    cudaGetSymbolAddress((void**)&pv, g_v);
    cudaGetSymbolAddress((void**)&pwh, g_wth);
    cudaGetSymbolAddress((void**)&pwl, g_wtl);

    const float invB = 1.0f / (float)B_;

    zero_stats_k<<<(5 * D_ + 255) / 256, 256>>>();
    wconv_k<<<D_ * D_ / 256, 256>>>(mg_w, 0);
    wconv_k<<<D_ * D_ / 256, 256>>>(ph_w1, 1);
    wconv_k<<<D_ * D_ / 256, 256>>>(ph_w2, 2);
    row_kernel<<<B_ / 8, 256>>>(image, text, wg_w1, wg_b1, wg_w2, wg_b2, conv_w, conv_b);

    colstats_k<<<256, 512>>>(image, B_, 0);
    colstats_k<<<256, 512>>>(px, B_, 1);
    finalize_k<<<1, 512>>>(0, ph_bn1_g, ph_bn1_b, invB);
    finalize_k<<<1, 512>>>(1, mg_bn_g, mg_bn_b, invB);

    gemm_mma<<<(B_ / 128) * 4, 256>>>(px, nullptr, B_, 1, 1,
                          pwh + 0 * D_ * D_, pwl + 0 * D_ * D_, mg_b, pf, 1);

    colstats_k<<<256, 512>>>(pf, B_, 2);
    finalize_k<<<1, 512>>>(2, ph_bn1_g, ph_bn1_b, invB);

    gemm_mma<<<(2 * B_ / 128) * 4, 256>>>(image, pf, B_, 0, 2,
                          pwh + 1 * D_ * D_, pwl + 1 * D_ * D_, ph_b1, pu, 1);

    colstats_k<<<256, 512>>>(pu, B_, 3);
    colstats_k<<<256, 512>>>(pu + (size_t)B_ * D_, B_, 4);
    finalize_k<<<1, 512>>>(3, ph_bn2_g, ph_bn2_b, invB);
    finalize_k<<<1, 512>>>(4, ph_bn2_g, ph_bn2_b, invB);

    gemm_mma<<<(2 * B_ / 128) * 4, 256>>>(pu, pu + (size_t)B_ * D_, B_, 3, 4,
                          pwh + 2 * D_ * D_, pwl + 2 * D_ * D_, ph_b2, pv, 0);

    l2norm_k<<<2 * B_ / 8, 256>>>(pv, out);
}